// round 5
// baseline (speedup 1.0000x reference)
#include <cuda_runtime.h>
#include <cuda_bf16.h>
#include <math.h>

// X [T=16384, H=2880] f32; W [E=128, H=2880] f32; bias [E=128] f32
// d_out f32: [0,T*4) softmax vals | [T*4,T*8) indices | [T*8,..) logits [T,E]
//
// sm_100 base ISA only (no tcgen05 on this toolchain target!).
// Kernel A: zero worklist counter.
// Kernel B: mma.sync bf16 split-precision (hi+lo, 3-pass) GEMM.
//   128x128 CTA tile, 512 threads (16 warps, each 32Mx32N), K staged 64 f32,
//   double-buffered SW128 smem tiles, ldmatrix.x4 fragment loads.
// Kernel C: exact compensated recompute of ambiguous tokens (worklist).

#define NTHREADS 512
#define BM 128
#define BN 128
#define LPAD 129
#define AMBIG_EPS 3e-4f

#define SM_BIAS   128            // 512 B of bias
#define SM_TILES  1024
#define TILE_B    16384          // 128 rows x 128 B (64 bf16)
#define BUF_B     (4 * TILE_B)   // Ah, Al, Bh, Bl
#define SMEM_TOTAL (SM_TILES + 2 * BUF_B)   // 132096 B

__device__ int g_count;
__device__ int g_list[65536];

extern __shared__ __align__(1024) char smem[];

__device__ __forceinline__ unsigned int smem_u32(const void* p) {
    unsigned int a;
    asm("{ .reg .u64 t; cvta.to.shared.u64 t, %1; cvt.u32.u64 %0, t; }"
        : "=r"(a) : "l"(p));
    return a;
}

__device__ __forceinline__ void ldm4(unsigned int* r, unsigned int addr) {
    asm volatile("ldmatrix.sync.aligned.m8n8.x4.shared.b16 {%0,%1,%2,%3}, [%4];"
                 : "=r"(r[0]), "=r"(r[1]), "=r"(r[2]), "=r"(r[3]) : "r"(addr));
}

__device__ __forceinline__ void mma16816(float* c, const unsigned int* a,
                                         unsigned int b0, unsigned int b1) {
    asm volatile(
        "mma.sync.aligned.m16n8k16.row.col.f32.bf16.bf16.f32 "
        "{%0,%1,%2,%3}, {%4,%5,%6,%7}, {%8,%9}, {%0,%1,%2,%3};"
        : "+f"(c[0]), "+f"(c[1]), "+f"(c[2]), "+f"(c[3])
        : "r"(a[0]), "r"(a[1]), "r"(a[2]), "r"(a[3]), "r"(b0), "r"(b1));
}

// 8 f32 (two float4) -> 16B hi + 16B lo bf16 vectors
__device__ __forceinline__ void cvt8(float4 v0, float4 v1, uint4& hi, uint4& lo) {
    unsigned int h0, h1, h2, h3;
    asm("cvt.rn.bf16x2.f32 %0, %1, %2;" : "=r"(h0) : "f"(v0.y), "f"(v0.x));
    asm("cvt.rn.bf16x2.f32 %0, %1, %2;" : "=r"(h1) : "f"(v0.w), "f"(v0.z));
    asm("cvt.rn.bf16x2.f32 %0, %1, %2;" : "=r"(h2) : "f"(v1.y), "f"(v1.x));
    asm("cvt.rn.bf16x2.f32 %0, %1, %2;" : "=r"(h3) : "f"(v1.w), "f"(v1.z));
    hi = make_uint4(h0, h1, h2, h3);
    float l0x = v0.x - __uint_as_float(h0 << 16);
    float l0y = v0.y - __uint_as_float(h0 & 0xFFFF0000u);
    float l0z = v0.z - __uint_as_float(h1 << 16);
    float l0w = v0.w - __uint_as_float(h1 & 0xFFFF0000u);
    float l1x = v1.x - __uint_as_float(h2 << 16);
    float l1y = v1.y - __uint_as_float(h2 & 0xFFFF0000u);
    float l1z = v1.z - __uint_as_float(h3 << 16);
    float l1w = v1.w - __uint_as_float(h3 & 0xFFFF0000u);
    unsigned int g0, g1, g2, g3;
    asm("cvt.rn.bf16x2.f32 %0, %1, %2;" : "=r"(g0) : "f"(l0y), "f"(l0x));
    asm("cvt.rn.bf16x2.f32 %0, %1, %2;" : "=r"(g1) : "f"(l0w), "f"(l0z));
    asm("cvt.rn.bf16x2.f32 %0, %1, %2;" : "=r"(g2) : "f"(l1y), "f"(l1x));
    asm("cvt.rn.bf16x2.f32 %0, %1, %2;" : "=r"(g3) : "f"(l1w), "f"(l1z));
    lo = make_uint4(g0, g1, g2, g3);
}

__global__ void zero_kernel() {
    if (threadIdx.x == 0) g_count = 0;
}

__global__ __launch_bounds__(NTHREADS, 1)
void gemm_kernel(const float* __restrict__ X,
                 const float* __restrict__ W,
                 const float* __restrict__ bias,
                 float* __restrict__ out_vals,
                 float* __restrict__ out_idx,
                 float* __restrict__ out_logits,
                 int T, int H)
{
    const int tid  = threadIdx.x;
    const int wid  = tid >> 5;
    const int lane = tid & 31;
    const int rowBase = blockIdx.x * BM;

    const int m_base = (wid >> 2) * 32;
    const int n_base = (wid & 3) * 32;

    if (tid < BN) ((float*)(smem + SM_BIAS))[tid] = bias[tid];

    // ---- loader mapping: row = tid>>2 (0..127), q = tid&3 (16 f32 each) ----
    const int lrow = tid >> 2;
    const int lq   = tid & 3;
    const float4* xptr = (const float4*)(X + (size_t)(rowBase + lrow) * H + lq * 16);
    const float4* wptr = (const float4*)(W + (size_t)lrow * H + lq * 16);
    const unsigned int st_row = (unsigned int)lrow << 7;   // row*128
    const unsigned int st_rx  = (unsigned int)(lrow & 7);

    // ---- ldmatrix per-lane address pieces ----
    // A (mt=0,1): row = m_base + mt*16 + ((lane>>3)&1)*8 + (lane&7); colofs = lane>>4
    // B (nt=0,1): row = n_base + nt*16 + (lane>>4)*8 + (lane&7);     colofs = (lane>>3)&1
    const int arow0 = m_base + ((lane >> 3) & 1) * 8 + (lane & 7);
    const int brow0 = n_base + (lane >> 4) * 8 + (lane & 7);
    const unsigned int acol = (unsigned int)(lane >> 4);
    const unsigned int bcol = (unsigned int)((lane >> 3) & 1);

    unsigned int aoff[2], axor[2], boff[2], bxor[2];
    #pragma unroll
    for (int mt = 0; mt < 2; mt++) {
        const int r = arow0 + mt * 16;
        aoff[mt] = (unsigned int)r << 7;
        axor[mt] = (unsigned int)(r & 7);
    }
    #pragma unroll
    for (int nt = 0; nt < 2; nt++) {
        const int r = brow0 + nt * 16;
        boff[nt] = (unsigned int)r << 7;
        bxor[nt] = (unsigned int)(r & 7);
    }

    const unsigned int sbuf0 = smem_u32(smem + SM_TILES);

    float acc[2][4][4];
    #pragma unroll
    for (int mt = 0; mt < 2; mt++)
        #pragma unroll
        for (int n8 = 0; n8 < 4; n8++)
            #pragma unroll
            for (int i = 0; i < 4; i++) acc[mt][n8][i] = 0.0f;

    const int nst = H / 64;   // 45

    float4 xv[4], wv[4];
    #pragma unroll
    for (int j = 0; j < 4; j++) { xv[j] = xptr[j]; wv[j] = wptr[j]; }

    // convert + store stage 0 into buffer 0
    {
        char* buf = smem + SM_TILES;
        uint4 hi, lo;
        cvt8(xv[0], xv[1], hi, lo);
        unsigned int o = st_row + (((unsigned int)(lq * 2) ^ st_rx) << 4);
        *(uint4*)(buf + o) = hi;               // Ah
        *(uint4*)(buf + TILE_B + o) = lo;      // Al
        cvt8(xv[2], xv[3], hi, lo);
        o = st_row + (((unsigned int)(lq * 2 + 1) ^ st_rx) << 4);
        *(uint4*)(buf + o) = hi;
        *(uint4*)(buf + TILE_B + o) = lo;
        cvt8(wv[0], wv[1], hi, lo);
        o = st_row + (((unsigned int)(lq * 2) ^ st_rx) << 4);
        *(uint4*)(buf + 2 * TILE_B + o) = hi;  // Bh
        *(uint4*)(buf + 3 * TILE_B + o) = lo;  // Bl
        cvt8(wv[2], wv[3], hi, lo);
        o = st_row + (((unsigned int)(lq * 2 + 1) ^ st_rx) << 4);
        *(uint4*)(buf + 2 * TILE_B + o) = hi;
        *(uint4*)(buf + 3 * TILE_B + o) = lo;
    }
    __syncthreads();

    for (int t = 0; t < nst; t++) {
        const unsigned int base = sbuf0 + (unsigned int)(t & 1) * BUF_B;

        if (t + 1 < nst) {
            const int ko = (t + 1) * 16;   // in float4 units
            #pragma unroll
            for (int j = 0; j < 4; j++) { xv[j] = xptr[ko + j]; wv[j] = wptr[ko + j]; }
        }

        // ---- MMA over 4 k16 chunks of this stage ----
        #pragma unroll
        for (int kk = 0; kk < 4; kk++) {
            const unsigned int kb = (unsigned int)(kk * 2);
            unsigned int ah[2][4], al[2][4], bh[2][4], bl[2][4];
            #pragma unroll
            for (int mt = 0; mt < 2; mt++) {
                unsigned int col = kb + acol;
                unsigned int ad = base + aoff[mt] + ((col ^ axor[mt]) << 4);
                ldm4(ah[mt], ad);
                ldm4(al[mt], ad + TILE_B);
            }
            #pragma unroll
            for (int nt = 0; nt < 2; nt++) {
                unsigned int col = kb + bcol;
                unsigned int bd = base + 2 * TILE_B + boff[nt] + ((col ^ bxor[nt]) << 4);
                ldm4(bh[nt], bd);
                ldm4(bl[nt], bd + TILE_B);
            }
            #pragma unroll
            for (int mt = 0; mt < 2; mt++)
                #pragma unroll
                for (int nt = 0; nt < 2; nt++)
                    #pragma unroll
                    for (int p = 0; p < 2; p++) {
                        float* c = acc[mt][nt * 2 + p];
                        mma16816(c, ah[mt], bh[nt][p * 2], bh[nt][p * 2 + 1]);
                        mma16816(c, ah[mt], bl[nt][p * 2], bl[nt][p * 2 + 1]);
                        mma16816(c, al[mt], bh[nt][p * 2], bh[nt][p * 2 + 1]);
                    }
        }

        if (t + 1 < nst) {
            __syncthreads();   // everyone done reading buf[(t+1)&1] (read at t-1)
            char* buf = smem + SM_TILES + ((t + 1) & 1) * BUF_B;
            uint4 hi, lo;
            cvt8(xv[0], xv[1], hi, lo);
            unsigned int o = st_row + (((unsigned int)(lq * 2) ^ st_rx) << 4);
            *(uint4*)(buf + o) = hi;
            *(uint4*)(buf + TILE_B + o) = lo;
            cvt8(xv[2], xv[3], hi, lo);
            o = st_row + (((unsigned int)(lq * 2 + 1) ^ st_rx) << 4);
            *(uint4*)(buf + o) = hi;
            *(uint4*)(buf + TILE_B + o) = lo;
            cvt8(wv[0], wv[1], hi, lo);
            o = st_row + (((unsigned int)(lq * 2) ^ st_rx) << 4);
            *(uint4*)(buf + 2 * TILE_B + o) = hi;
            *(uint4*)(buf + 3 * TILE_B + o) = lo;
            cvt8(wv[2], wv[3], hi, lo);
            o = st_row + (((unsigned int)(lq * 2 + 1) ^ st_rx) << 4);
            *(uint4*)(buf + 2 * TILE_B + o) = hi;
            *(uint4*)(buf + 3 * TILE_B + o) = lo;
            __syncthreads();
        }
    }
    __syncthreads();   // done with tile buffers; reuse as logits

    // ---------------- Epilogue ----------------
    float* Ls = (float*)(smem + SM_TILES);            // [128][LPAD]
    const float* bsm = (const float*)(smem + SM_BIAS);

    #pragma unroll
    for (int mt = 0; mt < 2; mt++) {
        const int r1 = m_base + mt * 16 + (lane >> 2);
        #pragma unroll
        for (int n8 = 0; n8 < 4; n8++) {
            const int c = n_base + n8 * 8 + (lane & 3) * 2;
            const float b0 = bsm[c], b1 = bsm[c + 1];
            Ls[r1 * LPAD + c]           = acc[mt][n8][0] + b0;
            Ls[r1 * LPAD + c + 1]       = acc[mt][n8][1] + b1;
            Ls[(r1 + 8) * LPAD + c]     = acc[mt][n8][2] + b0;
            Ls[(r1 + 8) * LPAD + c + 1] = acc[mt][n8][3] + b1;
        }
    }
    __syncthreads();

    // logits to gmem: 4096 float4
    #pragma unroll
    for (int i = 0; i < 8; i++) {
        const int idx = tid + NTHREADS * i;
        const int row = idx >> 5;
        const int c4  = idx & 31;
        float4 v;
        v.x = Ls[row * LPAD + c4 * 4 + 0];
        v.y = Ls[row * LPAD + c4 * 4 + 1];
        v.z = Ls[row * LPAD + c4 * 4 + 2];
        v.w = Ls[row * LPAD + c4 * 4 + 3];
        *(float4*)&out_logits[(size_t)(rowBase + row) * BN + c4 * 4] = v;
    }

    // top-5 + softmax + ambiguity worklist (threads 0..127, one token each)
    if (tid < BM) {
        const int token = rowBase + tid;
        const float* row = &Ls[tid * LPAD];
        float tv[5] = {-1e30f, -1e30f, -1e30f, -1e30f, -1e30f};
        int   ti[5] = {0, 0, 0, 0, 0};
        for (int e = 0; e < BN; e++) {
            float val = row[e];
            if (val > tv[4]) {
                tv[4] = val; ti[4] = e;
                #pragma unroll
                for (int s = 4; s > 0; s--) {
                    if (tv[s] > tv[s - 1]) {
                        float fv = tv[s]; tv[s] = tv[s-1]; tv[s-1] = fv;
                        int   fi = ti[s]; ti[s] = ti[s-1]; ti[s-1] = fi;
                    }
                }
            }
        }
        bool ambig = (tv[0] - tv[1] < AMBIG_EPS) |
                     (tv[1] - tv[2] < AMBIG_EPS) |
                     (tv[2] - tv[3] < AMBIG_EPS) |
                     (tv[3] - tv[4] < AMBIG_EPS);
        if (ambig) {
            int p = atomicAdd(&g_count, 1);
            g_list[p] = token;
        }
        const float mx = tv[0];
        float e0 = expf(tv[0] - mx);
        float e1 = expf(tv[1] - mx);
        float e2 = expf(tv[2] - mx);
        float e3 = expf(tv[3] - mx);
        const float inv = 1.0f / (e0 + e1 + e2 + e3);
        out_vals[(size_t)token * 4 + 0] = e0 * inv;
        out_vals[(size_t)token * 4 + 1] = e1 * inv;
        out_vals[(size_t)token * 4 + 2] = e2 * inv;
        out_vals[(size_t)token * 4 + 3] = e3 * inv;
        out_idx[(size_t)token * 4 + 0] = (float)ti[0];
        out_idx[(size_t)token * 4 + 1] = (float)ti[1];
        out_idx[(size_t)token * 4 + 2] = (float)ti[2];
        out_idx[(size_t)token * 4 + 3] = (float)ti[3];
    }
}

// ---------------- Refinement over compacted worklist ----------------
__global__ __launch_bounds__(256, 4)
void refine_kernel(const float* __restrict__ X,
                   const float* __restrict__ W,
                   const float* __restrict__ bias,
                   float* __restrict__ out_vals,
                   float* __restrict__ out_idx,
                   int T, int H)
{
    const int cnt = *(volatile int*)&g_count;
    __shared__ double s_partial[256];
    __shared__ double s_logit[128];

    const int e = threadIdx.x >> 1;
    const int h = threadIdx.x & 1;
    const int half = H >> 1;
    const int nq = half >> 2;

    for (int it = blockIdx.x; it < cnt; it += gridDim.x) {
        const int token = g_list[it];
        const float4* xr = (const float4*)(X + (size_t)token * H + (size_t)h * half);
        const float4* wr = (const float4*)(W + (size_t)e * H + (size_t)h * half);

        float s[4] = {0.f, 0.f, 0.f, 0.f};
        float c[4] = {0.f, 0.f, 0.f, 0.f};
        for (int i = 0; i < nq; i++) {
            float4 xvv = xr[i];
            float4 wvv = wr[i];
            float a4[4] = {xvv.x, xvv.y, xvv.z, xvv.w};
            float b4[4] = {wvv.x, wvv.y, wvv.z, wvv.w};
            #pragma unroll
            for (int l = 0; l < 4; l++) {
                float p  = a4[l] * b4[l];
                float pe = fmaf(a4[l], b4[l], -p);
                float t2 = s[l] + p;
                float z  = t2 - s[l];
                float er = (s[l] - (t2 - z)) + (p - z);
                s[l] = t2;
                c[l] += er + pe;
            }
        }
        double tot = 0.0;
        #pragma unroll
        for (int l = 0; l < 4; l++) tot += (double)s[l] + (double)c[l];
        s_partial[threadIdx.x] = tot;
        __syncthreads();

        if (h == 0)
            s_logit[e] = s_partial[2 * e] + s_partial[2 * e + 1] + (double)bias[e];
        __syncthreads();

        if (threadIdx.x == 0) {
            double tv[4] = {-1e300, -1e300, -1e300, -1e300};
            int    ti[4] = {0, 0, 0, 0};
            for (int k = 0; k < 128; k++) {
                double val = s_logit[k];
                if (val > tv[3]) {
                    tv[3] = val; ti[3] = k;
                    #pragma unroll
                    for (int s2 = 3; s2 > 0; s2--) {
                        if (tv[s2] > tv[s2 - 1]) {
                            double fv = tv[s2]; tv[s2] = tv[s2-1]; tv[s2-1] = fv;
                            int    fi = ti[s2]; ti[s2] = ti[s2-1]; ti[s2-1] = fi;
                        }
                    }
                }
            }
            float v0 = (float)tv[0], v1 = (float)tv[1],
                  v2 = (float)tv[2], v3 = (float)tv[3];
            float e0 = expf(v0 - v0);
            float e1 = expf(v1 - v0);
            float e2 = expf(v2 - v0);
            float e3 = expf(v3 - v0);
            float inv = 1.0f / (e0 + e1 + e2 + e3);
            out_vals[(size_t)token * 4 + 0] = e0 * inv;
            out_vals[(size_t)token * 4 + 1] = e1 * inv;
            out_vals[(size_t)token * 4 + 2] = e2 * inv;
            out_vals[(size_t)token * 4 + 3] = e3 * inv;
            out_idx[(size_t)token * 4 + 0] = (float)ti[0];
            out_idx[(size_t)token * 4 + 1] = (float)ti[1];
            out_idx[(size_t)token * 4 + 2] = (float)ti[2];
            out_idx[(size_t)token * 4 + 3] = (float)ti[3];
        }
        __syncthreads();
    }
}

extern "C" void kernel_launch(void* const* d_in, const int* in_sizes, int n_in,
                              void* d_out, int out_size)
{
    const float* X    = (const float*)d_in[0];
    const float* W    = (const float*)d_in[1];
    const float* bias = (const float*)d_in[2];

    const int E = in_sizes[2];          // 128
    const int H = in_sizes[1] / E;      // 2880
    const int T = in_sizes[0] / H;      // 16384

    float* out        = (float*)d_out;
    float* out_vals   = out;
    float* out_idx    = out + (size_t)T * 4;
    float* out_logits = out + (size_t)T * 8;

    cudaFuncSetAttribute(gemm_kernel,
                         cudaFuncAttributeMaxDynamicSharedMemorySize,
                         SMEM_TOTAL);

    zero_kernel<<<1, 32>>>();
    gemm_kernel<<<T / BM, NTHREADS, SMEM_TOTAL>>>(
        X, W, bias, out_vals, out_idx, out_logits, T, H);
    refine_kernel<<<256, 256>>>(X, W, bias, out_vals, out_idx, T, H);
}